// round 4
// baseline (speedup 1.0000x reference)
#include <cuda_runtime.h>
#include <cuda_bf16.h>
#include <cstdint>

#define NPTS 8192
#define KNN  8

// ---------------- scratch (device globals: no allocations allowed) ----------
__device__ int   g_knn[NPTS * KNN];
__device__ float g_x1 [NPTS * 128];   // edgeconv1 output (post-relu)
__device__ float g_A  [NPTS * 128];   // x1 @ (W3a - W3b) + b3
__device__ float g_B  [NPTS * 128];   // x1 @ W3b
__device__ unsigned short g_w4hi[256 * 128];  // W4^T split-high, [c][k] bf16 bits
__device__ unsigned short g_w4lo[256 * 128];  // W4^T split-low,  [c][k] bf16 bits

#define CSWAP(a,b) { if ((b) < (a)) { unsigned long long _t=(a); (a)=(b); (b)=_t; } }

// ---------------- helpers ----------------------------------------------------
__device__ __forceinline__ uint32_t smem_u32(const void* p) {
    uint32_t a;
    asm("{ .reg .u64 t; cvta.to.shared.u64 t, %1; cvt.u32.u64 %0, t; }"
        : "=r"(a) : "l"(p));
    return a;
}

// round-to-nearest bf16 split: f = hi + lo (both representable as bf16)
__device__ __forceinline__ void bf16_split(float f, uint32_t& hi, uint32_t& lo) {
    uint32_t u = __float_as_uint(f);
    uint32_t hb = (u + 0x7FFFu + ((u >> 16) & 1u)) & 0xFFFF0000u;
    float fl = f - __uint_as_float(hb);
    uint32_t v = __float_as_uint(fl);
    uint32_t lb = (v + 0x7FFFu + ((v >> 16) & 1u));
    hi = hb >> 16;
    lo = lb >> 16;
}

// ---------------- Kernel 1: KNN (one warp per query) ------------------------
// scan compares d' = s2[j] - 2*q.x[j] (q2 offset dropped: constant per query).
__global__ __launch_bounds__(256) void knn_kernel(const float* __restrict__ pts) {
    const int TS = 2048;
    __shared__ float4 sp[TS];
    const int lane = threadIdx.x & 31;
    const int warp = threadIdx.x >> 5;
    const int qi = blockIdx.x * 8 + warp;

    const float qx = pts[qi*3+0], qy = pts[qi*3+1], qz = pts[qi*3+2];
    const float ax = -2.0f*qx, ay = -2.0f*qy, az = -2.0f*qz;

    // sentinel = orderable(FLT_MAX) so unpack stays a valid float
    const unsigned long long SENT = 0xFF7FFFFFFFFFFFFFULL;
    unsigned long long k0=SENT,k1=SENT,k2=SENT,k3=SENT,
                       k4=SENT,k5=SENT,k6=SENT,k7=SENT;
    float d7 = 3.4028235e38f;

    for (int base = 0; base < NPTS; base += TS) {
        __syncthreads();
        for (int t = threadIdx.x; t < TS; t += 256) {
            float x = pts[(base+t)*3+0];
            float y = pts[(base+t)*3+1];
            float z = pts[(base+t)*3+2];
            sp[t] = make_float4(x, y, z, x*x + y*y + z*z);
        }
        __syncthreads();
        #pragma unroll 4
        for (int j = lane; j < TS; j += 32) {
            float4 p = sp[j];
            float d = fmaf(ax, p.x, fmaf(ay, p.y, fmaf(az, p.z, p.w)));
            if (d < d7) {
                unsigned int ob = __float_as_uint(d);
                ob ^= ((unsigned int)((int)ob >> 31)) | 0x80000000u;
                unsigned long long key =
                    ((unsigned long long)ob << 32) | (unsigned int)(base + j);
                k7 = key;
                CSWAP(k6,k7); CSWAP(k5,k6); CSWAP(k4,k5); CSWAP(k3,k4);
                CSWAP(k2,k3); CSWAP(k1,k2); CSWAP(k0,k1);
                unsigned int hb = (unsigned int)(k7 >> 32);
                unsigned int s = (hb & 0x80000000u) ? (hb ^ 0x80000000u) : ~hb;
                d7 = __uint_as_float(s);
            }
        }
    }
    #pragma unroll
    for (int r = 0; r < KNN; r++) {
        unsigned long long m = k0;
        #pragma unroll
        for (int off = 16; off; off >>= 1) {
            unsigned long long o = __shfl_xor_sync(0xFFFFFFFFu, m, off);
            if (o < m) m = o;
        }
        if (k0 == m) { k0=k1; k1=k2; k2=k3; k3=k4; k4=k5; k5=k6; k6=k7; k7=SENT; }
        if (lane == 0) g_knn[qi*KNN + r] = (int)(m & 0xFFFFFFFFu);
    }
}

// ---------------- Kernel 2: EdgeConv1 (16 points per block, 512 thr) --------
__global__ __launch_bounds__(512) void conv1_kernel(
    const float* __restrict__ pts,
    const float* __restrict__ W1, const float* __restrict__ b1,
    const float* __restrict__ W2, const float* __restrict__ b2)
{
    __shared__ float se[16][8][6];
    __shared__ float sh[16][8][64];
    __shared__ float sw2[64*128];          // staged W2 (32KB)
    const int t  = threadIdx.x;
    const int p0 = blockIdx.x * 16;

    #pragma unroll
    for (int r = 0; r < 4; r++)            // 2048 float4 = 8192 floats
        ((float4*)sw2)[t + r*512] = ((const float4*)W2)[t + r*512];

    if (t < 128) {
        int p = t >> 3, e = t & 7;
        int i = p0 + p;
        int j = g_knn[i*KNN + e];
        float xi0 = pts[i*3+0], xi1 = pts[i*3+1], xi2 = pts[i*3+2];
        float xj0 = pts[j*3+0], xj1 = pts[j*3+1], xj2 = pts[j*3+2];
        se[p][e][0] = xi0; se[p][e][1] = xi1; se[p][e][2] = xi2;
        se[p][e][3] = xj0 - xi0; se[p][e][4] = xj1 - xi1; se[p][e][5] = xj2 - xi2;
    }
    __syncthreads();

    #pragma unroll
    for (int r = 0; r < 16; r++) {
        int id = t + r*512;                // 0..8191
        int p = id >> 9, e = (id >> 6) & 7, u = id & 63;
        float acc = b1[u];
        #pragma unroll
        for (int f = 0; f < 6; f++) acc += se[p][e][f] * W1[f*64 + u];
        sh[p][e][u] = fmaxf(acc, 0.0f);
    }
    __syncthreads();

    const int p  = t >> 5;                 // warp == point (16 warps)
    const int c0 = (t & 31) * 4;
    float acc[8][4];
    #pragma unroll
    for (int e = 0; e < 8; e++)
        { acc[e][0]=0.f; acc[e][1]=0.f; acc[e][2]=0.f; acc[e][3]=0.f; }

    #pragma unroll 4
    for (int u = 0; u < 64; u++) {
        float4 w = *(const float4*)(sw2 + u*128 + c0);
        #pragma unroll
        for (int e = 0; e < 8; e++) {
            float hv = sh[p][e][u];
            acc[e][0] += hv*w.x; acc[e][1] += hv*w.y;
            acc[e][2] += hv*w.z; acc[e][3] += hv*w.w;
        }
    }
    const int i = p0 + p;
    #pragma unroll
    for (int cc = 0; cc < 4; cc++) {
        float m = acc[0][cc];
        #pragma unroll
        for (int e = 1; e < 8; e++) m = fmaxf(m, acc[e][cc]);
        m += b2[c0+cc];
        g_x1[i*128 + c0 + cc] = fmaxf(m, 0.0f);
    }
}

// ---------------- Kernel 3: precompute A, Bv for EdgeConv2 (256 thr) --------
__global__ __launch_bounds__(256) void pre2_kernel(
    const float* __restrict__ W3, const float* __restrict__ b3)
{
    __shared__ float sx[16*128];
    const int t  = threadIdx.x;
    const int p0 = blockIdx.x * 16;

    #pragma unroll
    for (int r = 0; r < 2; r++)            // 512 float4 = 2048 floats
        ((float4*)sx)[t + r*256] = ((const float4*)(g_x1 + p0*128))[t + r*256];
    __syncthreads();

    const int c = t & 127;
    const int half = t >> 7;               // warps 0-3: A, warps 4-7: B
    float acc[16];
    #pragma unroll
    for (int p = 0; p < 16; p++) acc[p] = 0.f;

    if (half == 0) {
        #pragma unroll 2
        for (int k = 0; k < 128; k++) {
            float wd = W3[k*128 + c] - W3[(k+128)*128 + c];
            #pragma unroll
            for (int p = 0; p < 16; p++) acc[p] += sx[p*128 + k] * wd;
        }
        float bb = b3[c];
        #pragma unroll
        for (int p = 0; p < 16; p++) g_A[(p0+p)*128 + c] = acc[p] + bb;
    } else {
        #pragma unroll 2
        for (int k = 0; k < 128; k++) {
            float wb = W3[(k+128)*128 + c];
            #pragma unroll
            for (int p = 0; p < 16; p++) acc[p] += sx[p*128 + k] * wb;
        }
        #pragma unroll
        for (int p = 0; p < 16; p++) g_B[(p0+p)*128 + c] = acc[p];
    }
}

// ---------------- Kernel 3b: split + transpose W4 into bf16 hi/lo -----------
__global__ __launch_bounds__(256) void w4split_kernel(const float* __restrict__ W4) {
    int k = blockIdx.x;
    int c = threadIdx.x;
    float w = W4[k*256 + c];
    uint32_t hi, lo;
    bf16_split(w, hi, lo);
    g_w4hi[c*128 + k] = (unsigned short)hi;
    g_w4lo[c*128 + k] = (unsigned short)lo;
}

// ---------------- Kernel 4: EdgeConv2 via mma.sync bf16-split GEMM ----------
// Per CTA: M=64 edge rows (8 points), N=128 channels (blockIdx.y half), K=128.
// 8 warps in a 4(M) x 2(N) grid; 2 CTAs/SM for phase overlap.
#define PADK 136
#define A_ELEMS (64  * PADK)
#define B_ELEMS (128 * PADK)
#define CONV2_SMEM ((2*A_ELEMS + 2*B_ELEMS) * 2)

__global__ __launch_bounds__(256, 2) void conv2m_kernel(
    const float* __restrict__ b4, float* __restrict__ out)
{
    extern __shared__ __align__(16) char smem[];
    __nv_bfloat16* sAh = (__nv_bfloat16*)smem;
    __nv_bfloat16* sAl = sAh + A_ELEMS;
    __nv_bfloat16* sBh = sAl + A_ELEMS;
    __nv_bfloat16* sBl = sBh + B_ELEMS;

    const int t    = threadIdx.x;
    const int lane = t & 31;
    const int w    = t >> 5;
    const int p0   = blockIdx.x * 8;
    const int c0   = blockIdx.y * 128;

    // ---- build B tiles ([n][k], pre-split in gmem) ----
    {
        const int n = t & 127;
        const int which = t >> 7;          // 0: hi, 1: lo
        const unsigned short* src = which ? g_w4lo : g_w4hi;
        const uint4* s4 = (const uint4*)(src + (size_t)(c0 + n) * 128);
        uint4* d4 = (uint4*)((which ? sBl : sBh) + n * PADK);
        #pragma unroll
        for (int kg = 0; kg < 16; kg++) d4[kg] = s4[kg];
    }
    // ---- build A tiles (gather + relu + split) ----
    {
        const int r = t >> 2, q = t & 3;   // row, quarter (32 floats each)
        const int i = p0 + (r >> 3);
        const int j = g_knn[i * KNN + (r & 7)];
        const float4* pa = (const float4*)(g_A + (size_t)i * 128 + q * 32);
        const float4* pb = (const float4*)(g_B + (size_t)j * 128 + q * 32);
        uint2* dh = (uint2*)(sAh + r * PADK + q * 32);
        uint2* dl = (uint2*)(sAl + r * PADK + q * 32);
        #pragma unroll
        for (int kg = 0; kg < 8; kg++) {
            float4 a = pa[kg];
            float4 b = pb[kg];
            float h0 = fmaxf(a.x + b.x, 0.0f);
            float h1 = fmaxf(a.y + b.y, 0.0f);
            float h2 = fmaxf(a.z + b.z, 0.0f);
            float h3 = fmaxf(a.w + b.w, 0.0f);
            uint32_t h0h,h0l,h1h,h1l,h2h,h2l,h3h,h3l;
            bf16_split(h0, h0h, h0l); bf16_split(h1, h1h, h1l);
            bf16_split(h2, h2h, h2l); bf16_split(h3, h3h, h3l);
            uint2 hw, lw;
            hw.x = h0h | (h1h << 16); hw.y = h2h | (h3h << 16);
            lw.x = h0l | (h1l << 16); lw.y = h2l | (h3l << 16);
            dh[kg] = hw; dl[kg] = lw;
        }
    }
    __syncthreads();

    // ---- MMA mainloop: warp tile 16(M) x 64(N) ----
    const int mw = w & 3, nw = w >> 2;
    const int m0 = mw * 16;
    const int n0 = nw * 64;
    float d[8][4];
    #pragma unroll
    for (int nt = 0; nt < 8; nt++)
        { d[nt][0]=0.f; d[nt][1]=0.f; d[nt][2]=0.f; d[nt][3]=0.f; }

    const uint32_t aoff = ((uint32_t)(m0 + (lane & 15)) * PADK +
                           ((lane >> 4) & 1) * 8) * 2;
    const uint32_t boff = ((uint32_t)(n0 + (lane & 7)) * PADK +
                           ((lane >> 3) & 1) * 8) * 2;

    const uint32_t sAh32 = smem_u32(sAh), sAl32 = smem_u32(sAl);
    const uint32_t sBh32 = smem_u32(sBh), sBl32 = smem_u32(sBl);

    #pragma unroll
    for (int pass = 0; pass < 3; pass++) {
        const uint32_t Ab = (pass == 2) ? sAl32 : sAh32;
        const uint32_t Bb = (pass == 1) ? sBl32 : sBh32;
        #pragma unroll
        for (int k16 = 0; k16 < 8; k16++) {
            const uint32_t kb = k16 * 32;
            uint32_t a0, a1, a2, a3;
            asm volatile(
                "ldmatrix.sync.aligned.m8n8.x4.shared.b16 {%0,%1,%2,%3}, [%4];"
                : "=r"(a0), "=r"(a1), "=r"(a2), "=r"(a3)
                : "r"(Ab + aoff + kb));
            #pragma unroll
            for (int nt = 0; nt < 8; nt++) {
                uint32_t b0, b1;
                asm volatile(
                    "ldmatrix.sync.aligned.m8n8.x2.shared.b16 {%0,%1}, [%2];"
                    : "=r"(b0), "=r"(b1)
                    : "r"(Bb + boff + (uint32_t)nt * (8 * PADK * 2) + kb));
                asm volatile(
                    "mma.sync.aligned.m16n8k16.row.col.f32.bf16.bf16.f32 "
                    "{%0,%1,%2,%3}, {%4,%5,%6,%7}, {%8,%9}, {%0,%1,%2,%3};"
                    : "+f"(d[nt][0]), "+f"(d[nt][1]), "+f"(d[nt][2]), "+f"(d[nt][3])
                    : "r"(a0), "r"(a1), "r"(a2), "r"(a3), "r"(b0), "r"(b1));
            }
        }
    }

    // ---- epilogue: max over 8 edge rows (lane bits [4:2]), write 2 points ----
    #pragma unroll
    for (int nt = 0; nt < 8; nt++) {
        float v0 = d[nt][0], v1 = d[nt][1], v2 = d[nt][2], v3 = d[nt][3];
        #pragma unroll
        for (int off = 4; off <= 16; off <<= 1) {
            v0 = fmaxf(v0, __shfl_xor_sync(0xFFFFFFFFu, v0, off));
            v1 = fmaxf(v1, __shfl_xor_sync(0xFFFFFFFFu, v1, off));
            v2 = fmaxf(v2, __shfl_xor_sync(0xFFFFFFFFu, v2, off));
            v3 = fmaxf(v3, __shfl_xor_sync(0xFFFFFFFFu, v3, off));
        }
        if (lane < 4) {
            const int c = c0 + n0 + nt * 8 + lane * 2;
            const float2 bb = *(const float2*)(b4 + c);
            float2 o0; o0.x = v0 + bb.x; o0.y = v1 + bb.y;
            float2 o1; o1.x = v2 + bb.x; o1.y = v3 + bb.y;
            *(float2*)(out + (size_t)(p0 + mw*2    ) * 256 + c) = o0;
            *(float2*)(out + (size_t)(p0 + mw*2 + 1) * 256 + c) = o1;
        }
    }
}

// ---------------- launch -----------------------------------------------------
extern "C" void kernel_launch(void* const* d_in, const int* in_sizes, int n_in,
                              void* d_out, int out_size) {
    const float* pts = (const float*)d_in[0];
    const float* W1  = (const float*)d_in[1];
    const float* b1  = (const float*)d_in[2];
    const float* W2  = (const float*)d_in[3];
    const float* b2  = (const float*)d_in[4];
    const float* W3  = (const float*)d_in[5];
    const float* b3  = (const float*)d_in[6];
    const float* W4  = (const float*)d_in[7];
    const float* b4  = (const float*)d_in[8];
    float* out = (float*)d_out;

    cudaFuncSetAttribute(conv2m_kernel,
                         cudaFuncAttributeMaxDynamicSharedMemorySize, CONV2_SMEM);

    knn_kernel    <<<NPTS/8, 256>>>(pts);
    conv1_kernel  <<<NPTS/16, 512>>>(pts, W1, b1, W2, b2);
    w4split_kernel<<<128, 256>>>(W4);
    pre2_kernel   <<<NPTS/16, 256>>>(W3, b3);
    conv2m_kernel <<<dim3(NPTS/8, 2), 256, CONV2_SMEM>>>(b4, out);
}

// round 5
// speedup vs baseline: 1.0689x; 1.0689x over previous
#include <cuda_runtime.h>
#include <cuda_bf16.h>
#include <cstdint>

#define NPTS 8192
#define KNN  8

// ---------------- scratch (device globals: no allocations allowed) ----------
__device__ int   g_knn[NPTS * KNN];
__device__ float g_x1 [NPTS * 128];   // edgeconv1 output (post-relu)
__device__ float g_A  [NPTS * 128];   // x1 @ (W3a - W3b) + b3
__device__ float g_B  [NPTS * 128];   // x1 @ W3b
__device__ unsigned short g_w4hi[256 * 128];  // W4^T split-high, [c][k] bf16 bits
__device__ unsigned short g_w4lo[256 * 128];  // W4^T split-low,  [c][k] bf16 bits

#define CSWAP(a,b) { if ((b) < (a)) { unsigned long long _t=(a); (a)=(b); (b)=_t; } }

// ---------------- helpers ----------------------------------------------------
__device__ __forceinline__ uint32_t smem_u32(const void* p) {
    uint32_t a;
    asm("{ .reg .u64 t; cvta.to.shared.u64 t, %1; cvt.u32.u64 %0, t; }"
        : "=r"(a) : "l"(p));
    return a;
}

// round-to-nearest bf16 split: f = hi + lo (both representable as bf16)
__device__ __forceinline__ void bf16_split(float f, uint32_t& hi, uint32_t& lo) {
    uint32_t u = __float_as_uint(f);
    uint32_t hb = (u + 0x7FFFu + ((u >> 16) & 1u)) & 0xFFFF0000u;
    float fl = f - __uint_as_float(hb);
    uint32_t v = __float_as_uint(fl);
    uint32_t lb = (v + 0x7FFFu + ((v >> 16) & 1u));
    hi = hb >> 16;
    lo = lb >> 16;
}

// ---------------- Kernel 1: KNN (one warp per query) ------------------------
__global__ __launch_bounds__(256) void knn_kernel(const float* __restrict__ pts) {
    const int TS = 2048;
    __shared__ float4 sp[TS];
    const int lane = threadIdx.x & 31;
    const int warp = threadIdx.x >> 5;
    const int qi = blockIdx.x * 8 + warp;

    const float qx = pts[qi*3+0], qy = pts[qi*3+1], qz = pts[qi*3+2];
    const float ax = -2.0f*qx, ay = -2.0f*qy, az = -2.0f*qz;

    const unsigned long long SENT = 0xFF7FFFFFFFFFFFFFULL;
    unsigned long long k0=SENT,k1=SENT,k2=SENT,k3=SENT,
                       k4=SENT,k5=SENT,k6=SENT,k7=SENT;
    float d7 = 3.4028235e38f;

    for (int base = 0; base < NPTS; base += TS) {
        __syncthreads();
        for (int t = threadIdx.x; t < TS; t += 256) {
            float x = pts[(base+t)*3+0];
            float y = pts[(base+t)*3+1];
            float z = pts[(base+t)*3+2];
            sp[t] = make_float4(x, y, z, x*x + y*y + z*z);
        }
        __syncthreads();
        #pragma unroll 4
        for (int j = lane; j < TS; j += 32) {
            float4 p = sp[j];
            float d = fmaf(ax, p.x, fmaf(ay, p.y, fmaf(az, p.z, p.w)));
            if (d < d7) {
                unsigned int ob = __float_as_uint(d);
                ob ^= ((unsigned int)((int)ob >> 31)) | 0x80000000u;
                unsigned long long key =
                    ((unsigned long long)ob << 32) | (unsigned int)(base + j);
                k7 = key;
                CSWAP(k6,k7); CSWAP(k5,k6); CSWAP(k4,k5); CSWAP(k3,k4);
                CSWAP(k2,k3); CSWAP(k1,k2); CSWAP(k0,k1);
                unsigned int hb = (unsigned int)(k7 >> 32);
                unsigned int s = (hb & 0x80000000u) ? (hb ^ 0x80000000u) : ~hb;
                d7 = __uint_as_float(s);
            }
        }
    }
    #pragma unroll
    for (int r = 0; r < KNN; r++) {
        unsigned long long m = k0;
        #pragma unroll
        for (int off = 16; off; off >>= 1) {
            unsigned long long o = __shfl_xor_sync(0xFFFFFFFFu, m, off);
            if (o < m) m = o;
        }
        if (k0 == m) { k0=k1; k1=k2; k2=k3; k3=k4; k4=k5; k5=k6; k6=k7; k7=SENT; }
        if (lane == 0) g_knn[qi*KNN + r] = (int)(m & 0xFFFFFFFFu);
    }
}

// ---------------- Kernel 2: EdgeConv1 (16 points per block, 512 thr) --------
__global__ __launch_bounds__(512) void conv1_kernel(
    const float* __restrict__ pts,
    const float* __restrict__ W1, const float* __restrict__ b1,
    const float* __restrict__ W2, const float* __restrict__ b2)
{
    __shared__ float se[16][8][6];
    __shared__ float sh[16][8][64];
    __shared__ float sw2[64*128];
    const int t  = threadIdx.x;
    const int p0 = blockIdx.x * 16;

    #pragma unroll
    for (int r = 0; r < 4; r++)
        ((float4*)sw2)[t + r*512] = ((const float4*)W2)[t + r*512];

    if (t < 128) {
        int p = t >> 3, e = t & 7;
        int i = p0 + p;
        int j = g_knn[i*KNN + e];
        float xi0 = pts[i*3+0], xi1 = pts[i*3+1], xi2 = pts[i*3+2];
        float xj0 = pts[j*3+0], xj1 = pts[j*3+1], xj2 = pts[j*3+2];
        se[p][e][0] = xi0; se[p][e][1] = xi1; se[p][e][2] = xi2;
        se[p][e][3] = xj0 - xi0; se[p][e][4] = xj1 - xi1; se[p][e][5] = xj2 - xi2;
    }
    __syncthreads();

    #pragma unroll
    for (int r = 0; r < 16; r++) {
        int id = t + r*512;
        int p = id >> 9, e = (id >> 6) & 7, u = id & 63;
        float acc = b1[u];
        #pragma unroll
        for (int f = 0; f < 6; f++) acc += se[p][e][f] * W1[f*64 + u];
        sh[p][e][u] = fmaxf(acc, 0.0f);
    }
    __syncthreads();

    const int p  = t >> 5;
    const int c0 = (t & 31) * 4;
    float acc[8][4];
    #pragma unroll
    for (int e = 0; e < 8; e++)
        { acc[e][0]=0.f; acc[e][1]=0.f; acc[e][2]=0.f; acc[e][3]=0.f; }

    #pragma unroll 4
    for (int u = 0; u < 64; u++) {
        float4 w = *(const float4*)(sw2 + u*128 + c0);
        #pragma unroll
        for (int e = 0; e < 8; e++) {
            float hv = sh[p][e][u];
            acc[e][0] += hv*w.x; acc[e][1] += hv*w.y;
            acc[e][2] += hv*w.z; acc[e][3] += hv*w.w;
        }
    }
    const int i = p0 + p;
    #pragma unroll
    for (int cc = 0; cc < 4; cc++) {
        float m = acc[0][cc];
        #pragma unroll
        for (int e = 1; e < 8; e++) m = fmaxf(m, acc[e][cc]);
        m += b2[c0+cc];
        g_x1[i*128 + c0 + cc] = fmaxf(m, 0.0f);
    }
}

// ---------------- Kernel 3: pre2 + fused W4 split/transpose -----------------
__global__ __launch_bounds__(256) void pre2_kernel(
    const float* __restrict__ W3, const float* __restrict__ b3,
    const float* __restrict__ W4)
{
    // fused w4split: blocks 0..127 handle one k-row of W4 each (independent)
    if (blockIdx.x < 128) {
        int k = blockIdx.x;
        int c = threadIdx.x;
        float w = W4[k*256 + c];
        uint32_t hi, lo;
        bf16_split(w, hi, lo);
        g_w4hi[c*128 + k] = (unsigned short)hi;
        g_w4lo[c*128 + k] = (unsigned short)lo;
    }

    __shared__ float sx[16*128];
    const int t  = threadIdx.x;
    const int p0 = blockIdx.x * 16;

    #pragma unroll
    for (int r = 0; r < 2; r++)
        ((float4*)sx)[t + r*256] = ((const float4*)(g_x1 + p0*128))[t + r*256];
    __syncthreads();

    const int c = t & 127;
    const int half = t >> 7;
    float acc[16];
    #pragma unroll
    for (int p = 0; p < 16; p++) acc[p] = 0.f;

    if (half == 0) {
        #pragma unroll 2
        for (int k = 0; k < 128; k++) {
            float wd = W3[k*128 + c] - W3[(k+128)*128 + c];
            #pragma unroll
            for (int p = 0; p < 16; p++) acc[p] += sx[p*128 + k] * wd;
        }
        float bb = b3[c];
        #pragma unroll
        for (int p = 0; p < 16; p++) g_A[(p0+p)*128 + c] = acc[p] + bb;
    } else {
        #pragma unroll 2
        for (int k = 0; k < 128; k++) {
            float wb = W3[(k+128)*128 + c];
            #pragma unroll
            for (int p = 0; p < 16; p++) acc[p] += sx[p*128 + k] * wb;
        }
        #pragma unroll
        for (int p = 0; p < 16; p++) g_B[(p0+p)*128 + c] = acc[p];
    }
}

// ---------------- Kernel 4: EdgeConv2 via mma.sync bf16-split GEMM ----------
// Per CTA: M=64 edge rows (8 points), FULL N=256 via two sequential B stages.
// A tiles built once and resident. 8 warps in 4(M) x 2(N) grid. 2 CTAs/SM.
#define PADK 136
#define A_ELEMS (64  * PADK)
#define B_ELEMS (128 * PADK)
#define CONV2_SMEM ((2*A_ELEMS + 2*B_ELEMS) * 2)

__global__ __launch_bounds__(256, 2) void conv2m_kernel(
    const float* __restrict__ b4, float* __restrict__ out)
{
    extern __shared__ __align__(16) char smem[];
    __nv_bfloat16* sAh = (__nv_bfloat16*)smem;
    __nv_bfloat16* sAl = sAh + A_ELEMS;
    __nv_bfloat16* sBh = sAl + A_ELEMS;
    __nv_bfloat16* sBl = sBh + B_ELEMS;

    const int t    = threadIdx.x;
    const int lane = t & 31;
    const int w    = t >> 5;
    const int p0   = blockIdx.x * 8;

    // ---- build A tiles once (gather + relu + split) ----
    {
        const int r = t >> 2, q = t & 3;
        const int i = p0 + (r >> 3);
        const int j = g_knn[i * KNN + (r & 7)];
        const float4* pa = (const float4*)(g_A + (size_t)i * 128 + q * 32);
        const float4* pb = (const float4*)(g_B + (size_t)j * 128 + q * 32);
        uint2* dh = (uint2*)(sAh + r * PADK + q * 32);
        uint2* dl = (uint2*)(sAl + r * PADK + q * 32);
        #pragma unroll
        for (int kg = 0; kg < 8; kg++) {
            float4 a = pa[kg];
            float4 b = pb[kg];
            float h0 = fmaxf(a.x + b.x, 0.0f);
            float h1 = fmaxf(a.y + b.y, 0.0f);
            float h2 = fmaxf(a.z + b.z, 0.0f);
            float h3 = fmaxf(a.w + b.w, 0.0f);
            uint32_t h0h,h0l,h1h,h1l,h2h,h2l,h3h,h3l;
            bf16_split(h0, h0h, h0l); bf16_split(h1, h1h, h1l);
            bf16_split(h2, h2h, h2l); bf16_split(h3, h3h, h3l);
            uint2 hw, lw;
            hw.x = h0h | (h1h << 16); hw.y = h2h | (h3h << 16);
            lw.x = h0l | (h1l << 16); lw.y = h2l | (h3l << 16);
            dh[kg] = hw; dl[kg] = lw;
        }
    }

    const int mw = w & 3, nwp = w >> 2;
    const int m0 = mw * 16;
    const int n0 = nwp * 64;

    const uint32_t sAh32 = smem_u32(sAh), sAl32 = smem_u32(sAl);
    const uint32_t sBh32 = smem_u32(sBh), sBl32 = smem_u32(sBl);

    const uint32_t aoff = ((uint32_t)(m0 + (lane & 15)) * PADK +
                           ((lane >> 4) & 1) * 8) * 2;
    // B x4: 2 n-tiles per load. lanes 0-15 -> nt pair lo (k0-7 / k8-15),
    // lanes 16-31 -> nt pair hi.
    const uint32_t boff = ((uint32_t)(n0 + ((lane >> 4) & 1) * 8 + (lane & 7)) * PADK +
                           ((lane >> 3) & 1) * 8) * 2;

    #pragma unroll
    for (int stage = 0; stage < 2; stage++) {
        // ---- build B tiles for this 128-channel stage ----
        {
            const int n = t & 127;
            const int which = t >> 7;      // 0: hi, 1: lo
            const unsigned short* src = which ? g_w4lo : g_w4hi;
            const uint4* s4 = (const uint4*)(src + (size_t)(stage*128 + n) * 128);
            uint4* d4 = (uint4*)((which ? sBl : sBh) + n * PADK);
            #pragma unroll
            for (int kg = 0; kg < 16; kg++) d4[kg] = s4[kg];
        }
        __syncthreads();

        float d[8][4];
        #pragma unroll
        for (int nt = 0; nt < 8; nt++)
            { d[nt][0]=0.f; d[nt][1]=0.f; d[nt][2]=0.f; d[nt][3]=0.f; }

        #pragma unroll
        for (int k16 = 0; k16 < 8; k16++) {
            const uint32_t kb = k16 * 32;
            uint32_t ah[4], al[4];
            asm volatile(
                "ldmatrix.sync.aligned.m8n8.x4.shared.b16 {%0,%1,%2,%3}, [%4];"
                : "=r"(ah[0]), "=r"(ah[1]), "=r"(ah[2]), "=r"(ah[3])
                : "r"(sAh32 + aoff + kb));
            asm volatile(
                "ldmatrix.sync.aligned.m8n8.x4.shared.b16 {%0,%1,%2,%3}, [%4];"
                : "=r"(al[0]), "=r"(al[1]), "=r"(al[2]), "=r"(al[3])
                : "r"(sAl32 + aoff + kb));
            uint32_t bh[16], bl[16];
            #pragma unroll
            for (int ntp = 0; ntp < 4; ntp++) {
                const uint32_t bo = boff + (uint32_t)ntp * (16 * PADK * 2) + kb;
                asm volatile(
                    "ldmatrix.sync.aligned.m8n8.x4.shared.b16 {%0,%1,%2,%3}, [%4];"
                    : "=r"(bh[ntp*4]), "=r"(bh[ntp*4+1]),
                      "=r"(bh[ntp*4+2]), "=r"(bh[ntp*4+3])
                    : "r"(sBh32 + bo));
                asm volatile(
                    "ldmatrix.sync.aligned.m8n8.x4.shared.b16 {%0,%1,%2,%3}, [%4];"
                    : "=r"(bl[ntp*4]), "=r"(bl[ntp*4+1]),
                      "=r"(bl[ntp*4+2]), "=r"(bl[ntp*4+3])
                    : "r"(sBl32 + bo));
            }
            #pragma unroll
            for (int nt = 0; nt < 8; nt++) {
                const int bi = (nt >> 1) * 4 + (nt & 1) * 2;
                asm volatile(
                    "mma.sync.aligned.m16n8k16.row.col.f32.bf16.bf16.f32 "
                    "{%0,%1,%2,%3}, {%4,%5,%6,%7}, {%8,%9}, {%0,%1,%2,%3};"
                    : "+f"(d[nt][0]), "+f"(d[nt][1]), "+f"(d[nt][2]), "+f"(d[nt][3])
                    : "r"(ah[0]), "r"(ah[1]), "r"(ah[2]), "r"(ah[3]),
                      "r"(bh[bi]), "r"(bh[bi+1]));
                asm volatile(
                    "mma.sync.aligned.m16n8k16.row.col.f32.bf16.bf16.f32 "
                    "{%0,%1,%2,%3}, {%4,%5,%6,%7}, {%8,%9}, {%0,%1,%2,%3};"
                    : "+f"(d[nt][0]), "+f"(d[nt][1]), "+f"(d[nt][2]), "+f"(d[nt][3])
                    : "r"(ah[0]), "r"(ah[1]), "r"(ah[2]), "r"(ah[3]),
                      "r"(bl[bi]), "r"(bl[bi+1]));
                asm volatile(
                    "mma.sync.aligned.m16n8k16.row.col.f32.bf16.bf16.f32 "
                    "{%0,%1,%2,%3}, {%4,%5,%6,%7}, {%8,%9}, {%0,%1,%2,%3};"
                    : "+f"(d[nt][0]), "+f"(d[nt][1]), "+f"(d[nt][2]), "+f"(d[nt][3])
                    : "r"(al[0]), "r"(al[1]), "r"(al[2]), "r"(al[3]),
                      "r"(bh[bi]), "r"(bh[bi+1]));
            }
        }

        // ---- epilogue: max over 8 edge rows (lane bits [4:2]) ----
        #pragma unroll
        for (int nt = 0; nt < 8; nt++) {
            float v0 = d[nt][0], v1 = d[nt][1], v2 = d[nt][2], v3 = d[nt][3];
            #pragma unroll
            for (int off = 4; off <= 16; off <<= 1) {
                v0 = fmaxf(v0, __shfl_xor_sync(0xFFFFFFFFu, v0, off));
                v1 = fmaxf(v1, __shfl_xor_sync(0xFFFFFFFFu, v1, off));
                v2 = fmaxf(v2, __shfl_xor_sync(0xFFFFFFFFu, v2, off));
                v3 = fmaxf(v3, __shfl_xor_sync(0xFFFFFFFFu, v3, off));
            }
            if (lane < 4) {
                const int c = stage*128 + n0 + nt * 8 + lane * 2;
                const float2 bb = *(const float2*)(b4 + c);
                float2 o0; o0.x = v0 + bb.x; o0.y = v1 + bb.y;
                float2 o1; o1.x = v2 + bb.x; o1.y = v3 + bb.y;
                *(float2*)(out + (size_t)(p0 + mw*2    ) * 256 + c) = o0;
                *(float2*)(out + (size_t)(p0 + mw*2 + 1) * 256 + c) = o1;
            }
        }
        __syncthreads();
    }
}

// ---------------- launch -----------------------------------------------------
extern "C" void kernel_launch(void* const* d_in, const int* in_sizes, int n_in,
                              void* d_out, int out_size) {
    const float* pts = (const float*)d_in[0];
    const float* W1  = (const float*)d_in[1];
    const float* b1  = (const float*)d_in[2];
    const float* W2  = (const float*)d_in[3];
    const float* b2  = (const float*)d_in[4];
    const float* W3  = (const float*)d_in[5];
    const float* b3  = (const float*)d_in[6];
    const float* W4  = (const float*)d_in[7];
    const float* b4  = (const float*)d_in[8];
    float* out = (float*)d_out;

    cudaFuncSetAttribute(conv2m_kernel,
                         cudaFuncAttributeMaxDynamicSharedMemorySize, CONV2_SMEM);

    knn_kernel  <<<NPTS/8, 256>>>(pts);
    conv1_kernel<<<NPTS/16, 512>>>(pts, W1, b1, W2, b2);
    pre2_kernel <<<NPTS/16, 256>>>(W3, b3, W4);
    conv2m_kernel<<<NPTS/8, 256, CONV2_SMEM>>>(b4, out);
}

// round 6
// speedup vs baseline: 1.4949x; 1.3986x over previous
#include <cuda_runtime.h>
#include <cuda_bf16.h>
#include <cstdint>

#define NPTS 8192
#define KNN  8

// ---------------- scratch (device globals: no allocations allowed) ----------
__device__ int   g_knn[NPTS * KNN];
__device__ float g_x1 [NPTS * 128];   // edgeconv1 output (post-relu)
__device__ float g_A  [NPTS * 128];   // x1 @ (W3a - W3b) + b3
__device__ float g_B  [NPTS * 128];   // x1 @ W3b
__device__ unsigned short g_w4hi[256 * 128];  // W4^T split-high, [c][k] bf16 bits
__device__ unsigned short g_w4lo[256 * 128];  // W4^T split-low,  [c][k] bf16 bits

// ---------------- helpers ----------------------------------------------------
__device__ __forceinline__ uint32_t smem_u32(const void* p) {
    uint32_t a;
    asm("{ .reg .u64 t; cvta.to.shared.u64 t, %1; cvt.u32.u64 %0, t; }"
        : "=r"(a) : "l"(p));
    return a;
}

// round-to-nearest bf16 split: f = hi + lo (both representable as bf16)
__device__ __forceinline__ void bf16_split(float f, uint32_t& hi, uint32_t& lo) {
    uint32_t u = __float_as_uint(f);
    uint32_t hb = (u + 0x7FFFu + ((u >> 16) & 1u)) & 0xFFFF0000u;
    float fl = f - __uint_as_float(hb);
    uint32_t v = __float_as_uint(fl);
    uint32_t lb = (v + 0x7FFFu + ((v >> 16) & 1u));
    hi = hb >> 16;
    lo = lb >> 16;
}

// ---------------- Kernel 1: KNN (one warp per query, batch-8 gated) ---------
__global__ __launch_bounds__(256) void knn_kernel(const float* __restrict__ pts) {
    const int TS = 2048;
    __shared__ float4 sp[TS];
    const int lane = threadIdx.x & 31;
    const int warp = threadIdx.x >> 5;
    const int qi = blockIdx.x * 8 + warp;

    const float qx = pts[qi*3+0], qy = pts[qi*3+1], qz = pts[qi*3+2];
    const float ax = -2.0f*qx, ay = -2.0f*qy, az = -2.0f*qz;

    const float INF = 3.4028235e38f;
    // sorted ascending top-8: distances + indices (per lane)
    float    ld[8]; unsigned int li[8];
    #pragma unroll
    for (int q = 0; q < 8; q++) { ld[q] = INF; li[q] = 0xFFFFFFFFu; }

    for (int base = 0; base < NPTS; base += TS) {
        __syncthreads();
        for (int t = threadIdx.x; t < TS; t += 256) {
            float x = pts[(base+t)*3+0];
            float y = pts[(base+t)*3+1];
            float z = pts[(base+t)*3+2];
            sp[t] = make_float4(x, y, z, x*x + y*y + z*z);
        }
        __syncthreads();

        for (int jb = 0; jb < TS; jb += 256) {
            float dd[8];
            #pragma unroll
            for (int q = 0; q < 8; q++) {
                float4 p = sp[jb + q*32 + lane];
                dd[q] = fmaf(ax, p.x, fmaf(ay, p.y, fmaf(az, p.z, p.w)));
            }
            float m01 = fminf(dd[0], dd[1]), m23 = fminf(dd[2], dd[3]);
            float m45 = fminf(dd[4], dd[5]), m67 = fminf(dd[6], dd[7]);
            float mn = fminf(fminf(m01, m23), fminf(m45, m67));
            if (mn < ld[7]) {
                #pragma unroll
                for (int q = 0; q < 8; q++) {
                    float x = dd[q];
                    if (x < ld[7]) {
                        unsigned int ix = (unsigned int)(base + jb + q*32 + lane);
                        ld[7] = x; li[7] = ix;
                        #pragma unroll
                        for (int s = 6; s >= 0; s--) {
                            bool sw = ld[s+1] < ld[s];
                            float  td = sw ? ld[s] : ld[s+1];
                            unsigned int ti = sw ? li[s] : li[s+1];
                            ld[s]   = sw ? ld[s+1] : ld[s];
                            li[s]   = sw ? li[s+1] : li[s];
                            ld[s+1] = td; li[s+1] = ti;
                        }
                    }
                }
            }
        }
    }

    // pack exact (ordered-dist, idx) keys and warp-merge 8 rounds
    unsigned long long k[8];
    #pragma unroll
    for (int q = 0; q < 8; q++) {
        unsigned int ob = __float_as_uint(ld[q]);
        ob ^= ((unsigned int)((int)ob >> 31)) | 0x80000000u;
        k[q] = ((unsigned long long)ob << 32) | li[q];
    }
    #pragma unroll
    for (int r = 0; r < KNN; r++) {
        unsigned long long m = k[0];
        #pragma unroll
        for (int off = 16; off; off >>= 1) {
            unsigned long long o = __shfl_xor_sync(0xFFFFFFFFu, m, off);
            if (o < m) m = o;
        }
        if (k[0] == m) {
            #pragma unroll
            for (int s = 0; s < 7; s++) k[s] = k[s+1];
            k[7] = 0xFFFFFFFFFFFFFFFFULL;
        }
        if (lane == 0) g_knn[qi*KNN + r] = (int)(m & 0xFFFFFFFFu);
    }
}

// ---------------- Kernel 2: EdgeConv1 (16 points per block, 512 thr) --------
__global__ __launch_bounds__(512) void conv1_kernel(
    const float* __restrict__ pts,
    const float* __restrict__ W1, const float* __restrict__ b1,
    const float* __restrict__ W2, const float* __restrict__ b2)
{
    __shared__ float se[16][8][6];
    __shared__ float sh[16][8][64];
    __shared__ float sw2[64*128];
    const int t  = threadIdx.x;
    const int p0 = blockIdx.x * 16;

    #pragma unroll
    for (int r = 0; r < 4; r++)
        ((float4*)sw2)[t + r*512] = ((const float4*)W2)[t + r*512];

    if (t < 128) {
        int p = t >> 3, e = t & 7;
        int i = p0 + p;
        int j = g_knn[i*KNN + e];
        float xi0 = pts[i*3+0], xi1 = pts[i*3+1], xi2 = pts[i*3+2];
        float xj0 = pts[j*3+0], xj1 = pts[j*3+1], xj2 = pts[j*3+2];
        se[p][e][0] = xi0; se[p][e][1] = xi1; se[p][e][2] = xi2;
        se[p][e][3] = xj0 - xi0; se[p][e][4] = xj1 - xi1; se[p][e][5] = xj2 - xi2;
    }
    __syncthreads();

    #pragma unroll
    for (int r = 0; r < 16; r++) {
        int id = t + r*512;
        int p = id >> 9, e = (id >> 6) & 7, u = id & 63;
        float acc = b1[u];
        #pragma unroll
        for (int f = 0; f < 6; f++) acc += se[p][e][f] * W1[f*64 + u];
        sh[p][e][u] = fmaxf(acc, 0.0f);
    }
    __syncthreads();

    const int p  = t >> 5;
    const int c0 = (t & 31) * 4;
    float acc[8][4];
    #pragma unroll
    for (int e = 0; e < 8; e++)
        { acc[e][0]=0.f; acc[e][1]=0.f; acc[e][2]=0.f; acc[e][3]=0.f; }

    #pragma unroll 4
    for (int u = 0; u < 64; u++) {
        float4 w = *(const float4*)(sw2 + u*128 + c0);
        #pragma unroll
        for (int e = 0; e < 8; e++) {
            float hv = sh[p][e][u];
            acc[e][0] += hv*w.x; acc[e][1] += hv*w.y;
            acc[e][2] += hv*w.z; acc[e][3] += hv*w.w;
        }
    }
    const int i = p0 + p;
    #pragma unroll
    for (int cc = 0; cc < 4; cc++) {
        float m = acc[0][cc];
        #pragma unroll
        for (int e = 1; e < 8; e++) m = fmaxf(m, acc[e][cc]);
        m += b2[c0+cc];
        g_x1[i*128 + c0 + cc] = fmaxf(m, 0.0f);
    }
}

// ---------------- Kernel 3: pre2 + fused W4 split/transpose -----------------
__global__ __launch_bounds__(256) void pre2_kernel(
    const float* __restrict__ W3, const float* __restrict__ b3,
    const float* __restrict__ W4)
{
    if (blockIdx.x < 128) {
        int k = blockIdx.x;
        int c = threadIdx.x;
        float w = W4[k*256 + c];
        uint32_t hi, lo;
        bf16_split(w, hi, lo);
        g_w4hi[c*128 + k] = (unsigned short)hi;
        g_w4lo[c*128 + k] = (unsigned short)lo;
    }

    __shared__ float sx[16*128];
    const int t  = threadIdx.x;
    const int p0 = blockIdx.x * 16;

    #pragma unroll
    for (int r = 0; r < 2; r++)
        ((float4*)sx)[t + r*256] = ((const float4*)(g_x1 + p0*128))[t + r*256];
    __syncthreads();

    const int c = t & 127;
    const int half = t >> 7;
    float acc[16];
    #pragma unroll
    for (int p = 0; p < 16; p++) acc[p] = 0.f;

    if (half == 0) {
        #pragma unroll 2
        for (int k = 0; k < 128; k++) {
            float wd = W3[k*128 + c] - W3[(k+128)*128 + c];
            #pragma unroll
            for (int p = 0; p < 16; p++) acc[p] += sx[p*128 + k] * wd;
        }
        float bb = b3[c];
        #pragma unroll
        for (int p = 0; p < 16; p++) g_A[(p0+p)*128 + c] = acc[p] + bb;
    } else {
        #pragma unroll 2
        for (int k = 0; k < 128; k++) {
            float wb = W3[(k+128)*128 + c];
            #pragma unroll
            for (int p = 0; p < 16; p++) acc[p] += sx[p*128 + k] * wb;
        }
        #pragma unroll
        for (int p = 0; p < 16; p++) g_B[(p0+p)*128 + c] = acc[p];
    }
}

// ---------------- Kernel 4: EdgeConv2 via mma.sync bf16-split GEMM ----------
// Per CTA: M=64 edge rows (8 points), FULL N=256 via two sequential B stages.
#define PADK 136
#define A_ELEMS (64  * PADK)
#define B_ELEMS (128 * PADK)
#define CONV2_SMEM ((2*A_ELEMS + 2*B_ELEMS) * 2)

__global__ __launch_bounds__(256, 2) void conv2m_kernel(
    const float* __restrict__ b4, float* __restrict__ out)
{
    extern __shared__ __align__(16) char smem[];
    __nv_bfloat16* sAh = (__nv_bfloat16*)smem;
    __nv_bfloat16* sAl = sAh + A_ELEMS;
    __nv_bfloat16* sBh = sAl + A_ELEMS;
    __nv_bfloat16* sBl = sBh + B_ELEMS;

    const int t    = threadIdx.x;
    const int lane = t & 31;
    const int w    = t >> 5;
    const int p0   = blockIdx.x * 8;

    // ---- build A tiles once (gather + relu + split) ----
    {
        const int r = t >> 2, q = t & 3;
        const int i = p0 + (r >> 3);
        const int j = g_knn[i * KNN + (r & 7)];
        const float4* pa = (const float4*)(g_A + (size_t)i * 128 + q * 32);
        const float4* pb = (const float4*)(g_B + (size_t)j * 128 + q * 32);
        uint2* dh = (uint2*)(sAh + r * PADK + q * 32);
        uint2* dl = (uint2*)(sAl + r * PADK + q * 32);
        #pragma unroll
        for (int kg = 0; kg < 8; kg++) {
            float4 a = pa[kg];
            float4 b = pb[kg];
            float h0 = fmaxf(a.x + b.x, 0.0f);
            float h1 = fmaxf(a.y + b.y, 0.0f);
            float h2 = fmaxf(a.z + b.z, 0.0f);
            float h3 = fmaxf(a.w + b.w, 0.0f);
            uint32_t h0h,h0l,h1h,h1l,h2h,h2l,h3h,h3l;
            bf16_split(h0, h0h, h0l); bf16_split(h1, h1h, h1l);
            bf16_split(h2, h2h, h2l); bf16_split(h3, h3h, h3l);
            uint2 hw, lw;
            hw.x = h0h | (h1h << 16); hw.y = h2h | (h3h << 16);
            lw.x = h0l | (h1l << 16); lw.y = h2l | (h3l << 16);
            dh[kg] = hw; dl[kg] = lw;
        }
    }

    const int mw = w & 3, nwp = w >> 2;
    const int m0 = mw * 16;
    const int n0 = nwp * 64;

    const uint32_t sAh32 = smem_u32(sAh), sAl32 = smem_u32(sAl);
    const uint32_t sBh32 = smem_u32(sBh), sBl32 = smem_u32(sBl);

    const uint32_t aoff = ((uint32_t)(m0 + (lane & 15)) * PADK +
                           ((lane >> 4) & 1) * 8) * 2;
    const uint32_t boff = ((uint32_t)(n0 + ((lane >> 4) & 1) * 8 + (lane & 7)) * PADK +
                           ((lane >> 3) & 1) * 8) * 2;

    #pragma unroll
    for (int stage = 0; stage < 2; stage++) {
        {
            const int n = t & 127;
            const int which = t >> 7;
            const unsigned short* src = which ? g_w4lo : g_w4hi;
            const uint4* s4 = (const uint4*)(src + (size_t)(stage*128 + n) * 128);
            uint4* d4 = (uint4*)((which ? sBl : sBh) + n * PADK);
            #pragma unroll
            for (int kg = 0; kg < 16; kg++) d4[kg] = s4[kg];
        }
        __syncthreads();

        float d[8][4];
        #pragma unroll
        for (int nt = 0; nt < 8; nt++)
            { d[nt][0]=0.f; d[nt][1]=0.f; d[nt][2]=0.f; d[nt][3]=0.f; }

        #pragma unroll
        for (int k16 = 0; k16 < 8; k16++) {
            const uint32_t kb = k16 * 32;
            uint32_t ah[4], al[4];
            asm volatile(
                "ldmatrix.sync.aligned.m8n8.x4.shared.b16 {%0,%1,%2,%3}, [%4];"
                : "=r"(ah[0]), "=r"(ah[1]), "=r"(ah[2]), "=r"(ah[3])
                : "r"(sAh32 + aoff + kb));
            asm volatile(
                "ldmatrix.sync.aligned.m8n8.x4.shared.b16 {%0,%1,%2,%3}, [%4];"
                : "=r"(al[0]), "=r"(al[1]), "=r"(al[2]), "=r"(al[3])
                : "r"(sAl32 + aoff + kb));
            uint32_t bh[16], bl[16];
            #pragma unroll
            for (int ntp = 0; ntp < 4; ntp++) {
                const uint32_t bo = boff + (uint32_t)ntp * (16 * PADK * 2) + kb;
                asm volatile(
                    "ldmatrix.sync.aligned.m8n8.x4.shared.b16 {%0,%1,%2,%3}, [%4];"
                    : "=r"(bh[ntp*4]), "=r"(bh[ntp*4+1]),
                      "=r"(bh[ntp*4+2]), "=r"(bh[ntp*4+3])
                    : "r"(sBh32 + bo));
                asm volatile(
                    "ldmatrix.sync.aligned.m8n8.x4.shared.b16 {%0,%1,%2,%3}, [%4];"
                    : "=r"(bl[ntp*4]), "=r"(bl[ntp*4+1]),
                      "=r"(bl[ntp*4+2]), "=r"(bl[ntp*4+3])
                    : "r"(sBl32 + bo));
            }
            #pragma unroll
            for (int nt = 0; nt < 8; nt++) {
                const int bi = (nt >> 1) * 4 + (nt & 1) * 2;
                asm volatile(
                    "mma.sync.aligned.m16n8k16.row.col.f32.bf16.bf16.f32 "
                    "{%0,%1,%2,%3}, {%4,%5,%6,%7}, {%8,%9}, {%0,%1,%2,%3};"
                    : "+f"(d[nt][0]), "+f"(d[nt][1]), "+f"(d[nt][2]), "+f"(d[nt][3])
                    : "r"(ah[0]), "r"(ah[1]), "r"(ah[2]), "r"(ah[3]),
                      "r"(bh[bi]), "r"(bh[bi+1]));
                asm volatile(
                    "mma.sync.aligned.m16n8k16.row.col.f32.bf16.bf16.f32 "
                    "{%0,%1,%2,%3}, {%4,%5,%6,%7}, {%8,%9}, {%0,%1,%2,%3};"
                    : "+f"(d[nt][0]), "+f"(d[nt][1]), "+f"(d[nt][2]), "+f"(d[nt][3])
                    : "r"(ah[0]), "r"(ah[1]), "r"(ah[2]), "r"(ah[3]),
                      "r"(bl[bi]), "r"(bl[bi+1]));
                asm volatile(
                    "mma.sync.aligned.m16n8k16.row.col.f32.bf16.bf16.f32 "
                    "{%0,%1,%2,%3}, {%4,%5,%6,%7}, {%8,%9}, {%0,%1,%2,%3};"
                    : "+f"(d[nt][0]), "+f"(d[nt][1]), "+f"(d[nt][2]), "+f"(d[nt][3])
                    : "r"(al[0]), "r"(al[1]), "r"(al[2]), "r"(al[3]),
                      "r"(bh[bi]), "r"(bh[bi+1]));
            }
        }

        #pragma unroll
        for (int nt = 0; nt < 8; nt++) {
            float v0 = d[nt][0], v1 = d[nt][1], v2 = d[nt][2], v3 = d[nt][3];
            #pragma unroll
            for (int off = 4; off <= 16; off <<= 1) {
                v0 = fmaxf(v0, __shfl_xor_sync(0xFFFFFFFFu, v0, off));
                v1 = fmaxf(v1, __shfl_xor_sync(0xFFFFFFFFu, v1, off));
                v2 = fmaxf(v2, __shfl_xor_sync(0xFFFFFFFFu, v2, off));
                v3 = fmaxf(v3, __shfl_xor_sync(0xFFFFFFFFu, v3, off));
            }
            if (lane < 4) {
                const int c = stage*128 + n0 + nt * 8 + lane * 2;
                const float2 bb = *(const float2*)(b4 + c);
                float2 o0; o0.x = v0 + bb.x; o0.y = v1 + bb.y;
                float2 o1; o1.x = v2 + bb.x; o1.y = v3 + bb.y;
                *(float2*)(out + (size_t)(p0 + mw*2    ) * 256 + c) = o0;
                *(float2*)(out + (size_t)(p0 + mw*2 + 1) * 256 + c) = o1;
            }
        }
        __syncthreads();
    }
}

// ---------------- launch -----------------------------------------------------
extern "C" void kernel_launch(void* const* d_in, const int* in_sizes, int n_in,
                              void* d_out, int out_size) {
    const float* pts = (const float*)d_in[0];
    const float* W1  = (const float*)d_in[1];
    const float* b1  = (const float*)d_in[2];
    const float* W2  = (const float*)d_in[3];
    const float* b2  = (const float*)d_in[4];
    const float* W3  = (const float*)d_in[5];
    const float* b3  = (const float*)d_in[6];
    const float* W4  = (const float*)d_in[7];
    const float* b4  = (const float*)d_in[8];
    float* out = (float*)d_out;

    cudaFuncSetAttribute(conv2m_kernel,
                         cudaFuncAttributeMaxDynamicSharedMemorySize, CONV2_SMEM);

    knn_kernel  <<<NPTS/8, 256>>>(pts);
    conv1_kernel<<<NPTS/16, 512>>>(pts, W1, b1, W2, b2);
    pre2_kernel <<<NPTS/16, 256>>>(W3, b3, W4);
    conv2m_kernel<<<NPTS/8, 256, CONV2_SMEM>>>(b4, out);
}

// round 7
// speedup vs baseline: 1.7819x; 1.1919x over previous
#include <cuda_runtime.h>
#include <cuda_fp16.h>
#include <cstdint>

#define NPTS 8192
#define KNN  8

// ---------------- scratch (device globals: no allocations allowed) ----------
__device__ int   g_knn[NPTS * KNN];
__device__ float g_x1 [NPTS * 128];   // edgeconv1 output (post-relu)
__device__ float g_A  [NPTS * 128];   // x1 @ (W3a - W3b) + b3
__device__ float g_B  [NPTS * 128];   // x1 @ W3b
__device__ unsigned short g_w4h[256 * 128];   // W4^T fp16, [c][k]

// ---------------- helpers ----------------------------------------------------
__device__ __forceinline__ uint32_t smem_u32(const void* p) {
    uint32_t a;
    asm("{ .reg .u64 t; cvta.to.shared.u64 t, %1; cvt.u32.u64 %0, t; }"
        : "=r"(a) : "l"(p));
    return a;
}

// ---------------- Kernel 1: KNN (one warp per query, batch-8 gated) ---------
__global__ __launch_bounds__(256) void knn_kernel(const float* __restrict__ pts) {
    const int TS = 2048;
    __shared__ float4 sp[TS];
    const int lane = threadIdx.x & 31;
    const int warp = threadIdx.x >> 5;
    const int qi = blockIdx.x * 8 + warp;

    const float qx = pts[qi*3+0], qy = pts[qi*3+1], qz = pts[qi*3+2];
    const float ax = -2.0f*qx, ay = -2.0f*qy, az = -2.0f*qz;

    const float INF = 3.4028235e38f;
    float    ld[8]; unsigned int li[8];
    #pragma unroll
    for (int q = 0; q < 8; q++) { ld[q] = INF; li[q] = 0xFFFFFFFFu; }

    for (int base = 0; base < NPTS; base += TS) {
        __syncthreads();
        for (int t = threadIdx.x; t < TS; t += 256) {
            float x = pts[(base+t)*3+0];
            float y = pts[(base+t)*3+1];
            float z = pts[(base+t)*3+2];
            sp[t] = make_float4(x, y, z, x*x + y*y + z*z);
        }
        __syncthreads();

        for (int jb = 0; jb < TS; jb += 256) {
            float dd[8];
            #pragma unroll
            for (int q = 0; q < 8; q++) {
                float4 p = sp[jb + q*32 + lane];
                dd[q] = fmaf(ax, p.x, fmaf(ay, p.y, fmaf(az, p.z, p.w)));
            }
            float m01 = fminf(dd[0], dd[1]), m23 = fminf(dd[2], dd[3]);
            float m45 = fminf(dd[4], dd[5]), m67 = fminf(dd[6], dd[7]);
            float mn = fminf(fminf(m01, m23), fminf(m45, m67));
            if (mn < ld[7]) {
                #pragma unroll
                for (int q = 0; q < 8; q++) {
                    float x = dd[q];
                    if (x < ld[7]) {
                        unsigned int ix = (unsigned int)(base + jb + q*32 + lane);
                        ld[7] = x; li[7] = ix;
                        #pragma unroll
                        for (int s = 6; s >= 0; s--) {
                            bool sw = ld[s+1] < ld[s];
                            float  td = sw ? ld[s] : ld[s+1];
                            unsigned int ti = sw ? li[s] : li[s+1];
                            ld[s]   = sw ? ld[s+1] : ld[s];
                            li[s]   = sw ? li[s+1] : li[s];
                            ld[s+1] = td; li[s+1] = ti;
                        }
                    }
                }
            }
        }
    }

    unsigned long long k[8];
    #pragma unroll
    for (int q = 0; q < 8; q++) {
        unsigned int ob = __float_as_uint(ld[q]);
        ob ^= ((unsigned int)((int)ob >> 31)) | 0x80000000u;
        k[q] = ((unsigned long long)ob << 32) | li[q];
    }
    #pragma unroll
    for (int r = 0; r < KNN; r++) {
        unsigned long long m = k[0];
        #pragma unroll
        for (int off = 16; off; off >>= 1) {
            unsigned long long o = __shfl_xor_sync(0xFFFFFFFFu, m, off);
            if (o < m) m = o;
        }
        if (k[0] == m) {
            #pragma unroll
            for (int s = 0; s < 7; s++) k[s] = k[s+1];
            k[7] = 0xFFFFFFFFFFFFFFFFULL;
        }
        if (lane == 0) g_knn[qi*KNN + r] = (int)(m & 0xFFFFFFFFu);
    }
}

// ---------------- Kernel 2: EdgeConv1 (16 points per block, 512 thr) --------
__global__ __launch_bounds__(512) void conv1_kernel(
    const float* __restrict__ pts,
    const float* __restrict__ W1, const float* __restrict__ b1,
    const float* __restrict__ W2, const float* __restrict__ b2)
{
    __shared__ float se[16][8][6];
    __shared__ float sh[64][16][8];        // [u][p][e] for vector phase-C reads
    __shared__ float sw2[64*128];
    const int t  = threadIdx.x;
    const int p0 = blockIdx.x * 16;

    #pragma unroll
    for (int r = 0; r < 4; r++)
        ((float4*)sw2)[t + r*512] = ((const float4*)W2)[t + r*512];

    if (t < 128) {
        int p = t >> 3, e = t & 7;
        int i = p0 + p;
        int j = g_knn[i*KNN + e];
        float xi0 = pts[i*3+0], xi1 = pts[i*3+1], xi2 = pts[i*3+2];
        float xj0 = pts[j*3+0], xj1 = pts[j*3+1], xj2 = pts[j*3+2];
        se[p][e][0] = xi0; se[p][e][1] = xi1; se[p][e][2] = xi2;
        se[p][e][3] = xj0 - xi0; se[p][e][4] = xj1 - xi1; se[p][e][5] = xj2 - xi2;
    }
    __syncthreads();

    #pragma unroll
    for (int r = 0; r < 16; r++) {
        int id = t + r*512;                // 0..8191
        int e = id & 7, p = (id >> 3) & 15, u = id >> 7;
        float acc = b1[u];
        #pragma unroll
        for (int f = 0; f < 6; f++) acc += se[p][e][f] * W1[f*64 + u];
        sh[u][p][e] = fmaxf(acc, 0.0f);
    }
    __syncthreads();

    const int p  = t >> 5;
    const int c0 = (t & 31) * 4;
    float acc[8][4];
    #pragma unroll
    for (int e = 0; e < 8; e++)
        { acc[e][0]=0.f; acc[e][1]=0.f; acc[e][2]=0.f; acc[e][3]=0.f; }

    #pragma unroll 4
    for (int u = 0; u < 64; u++) {
        float4 w   = *(const float4*)(sw2 + u*128 + c0);
        float4 e03 = *(const float4*)&sh[u][p][0];
        float4 e47 = *(const float4*)&sh[u][p][4];
        acc[0][0] += e03.x*w.x; acc[0][1] += e03.x*w.y; acc[0][2] += e03.x*w.z; acc[0][3] += e03.x*w.w;
        acc[1][0] += e03.y*w.x; acc[1][1] += e03.y*w.y; acc[1][2] += e03.y*w.z; acc[1][3] += e03.y*w.w;
        acc[2][0] += e03.z*w.x; acc[2][1] += e03.z*w.y; acc[2][2] += e03.z*w.z; acc[2][3] += e03.z*w.w;
        acc[3][0] += e03.w*w.x; acc[3][1] += e03.w*w.y; acc[3][2] += e03.w*w.z; acc[3][3] += e03.w*w.w;
        acc[4][0] += e47.x*w.x; acc[4][1] += e47.x*w.y; acc[4][2] += e47.x*w.z; acc[4][3] += e47.x*w.w;
        acc[5][0] += e47.y*w.x; acc[5][1] += e47.y*w.y; acc[5][2] += e47.y*w.z; acc[5][3] += e47.y*w.w;
        acc[6][0] += e47.z*w.x; acc[6][1] += e47.z*w.y; acc[6][2] += e47.z*w.z; acc[6][3] += e47.z*w.w;
        acc[7][0] += e47.w*w.x; acc[7][1] += e47.w*w.y; acc[7][2] += e47.w*w.z; acc[7][3] += e47.w*w.w;
    }
    const int i = p0 + p;
    #pragma unroll
    for (int cc = 0; cc < 4; cc++) {
        float m = acc[0][cc];
        #pragma unroll
        for (int e = 1; e < 8; e++) m = fmaxf(m, acc[e][cc]);
        m += b2[c0+cc];
        g_x1[i*128 + c0 + cc] = fmaxf(m, 0.0f);
    }
}

// ---------------- Kernel 3: pre2 + fused W4 fp16 transpose ------------------
__global__ __launch_bounds__(256) void pre2_kernel(
    const float* __restrict__ W3, const float* __restrict__ b3,
    const float* __restrict__ W4)
{
    if (blockIdx.x < 128) {
        int k = blockIdx.x;
        int c = threadIdx.x;
        __half h = __float2half_rn(W4[k*256 + c]);
        g_w4h[c*128 + k] = __half_as_ushort(h);
    }

    __shared__ float sx[16*128];
    const int t  = threadIdx.x;
    const int p0 = blockIdx.x * 16;

    #pragma unroll
    for (int r = 0; r < 2; r++)
        ((float4*)sx)[t + r*256] = ((const float4*)(g_x1 + p0*128))[t + r*256];
    __syncthreads();

    const int c = t & 127;
    const int half = t >> 7;
    float acc[16];
    #pragma unroll
    for (int p = 0; p < 16; p++) acc[p] = 0.f;

    if (half == 0) {
        #pragma unroll 2
        for (int k = 0; k < 128; k++) {
            float wd = W3[k*128 + c] - W3[(k+128)*128 + c];
            #pragma unroll
            for (int p = 0; p < 16; p++) acc[p] += sx[p*128 + k] * wd;
        }
        float bb = b3[c];
        #pragma unroll
        for (int p = 0; p < 16; p++) g_A[(p0+p)*128 + c] = acc[p] + bb;
    } else {
        #pragma unroll 2
        for (int k = 0; k < 128; k++) {
            float wb = W3[(k+128)*128 + c];
            #pragma unroll
            for (int p = 0; p < 16; p++) acc[p] += sx[p*128 + k] * wb;
        }
        #pragma unroll
        for (int p = 0; p < 16; p++) g_B[(p0+p)*128 + c] = acc[p];
    }
}

// ---------------- Kernel 4: EdgeConv2 via mma.sync fp16 single-pass ---------
// Per CTA: M=64 edge rows (8 points), FULL N=256 in one stage.
// 8 warps = 2(M) x 4(N), warp tile 32M x 64N. fp32 accum.
#define PADK 136
#define A_ELEMS (64  * PADK)
#define B_ELEMS (256 * PADK)
#define CONV2_SMEM ((A_ELEMS + B_ELEMS) * 2)

__global__ __launch_bounds__(256, 2) void conv2m_kernel(
    const float* __restrict__ b4, float* __restrict__ out)
{
    extern __shared__ __align__(16) char smem[];
    __half* sA = (__half*)smem;
    __half* sB = sA + A_ELEMS;

    const int t    = threadIdx.x;
    const int lane = t & 31;
    const int w    = t >> 5;
    const int p0   = blockIdx.x * 8;

    // ---- build B tile: full W4^T fp16, [n=256][k=128] ----
    {
        const uint4* s4 = (const uint4*)(g_w4h + (size_t)t * 128);
        uint4* d4 = (uint4*)(sB + t * PADK);
        #pragma unroll
        for (int kg = 0; kg < 16; kg++) d4[kg] = s4[kg];
    }
    // ---- build A tile (gather + relu -> fp16) ----
    {
        const int r = t >> 2, q = t & 3;
        const int i = p0 + (r >> 3);
        const int j = g_knn[i * KNN + (r & 7)];
        const float4* pa = (const float4*)(g_A + (size_t)i * 128 + q * 32);
        const float4* pb = (const float4*)(g_B + (size_t)j * 128 + q * 32);
        uint2* dh = (uint2*)(sA + r * PADK + q * 32);
        #pragma unroll
        for (int kg = 0; kg < 8; kg++) {
            float4 a = pa[kg];
            float4 b = pb[kg];
            float h0 = fmaxf(a.x + b.x, 0.0f);
            float h1 = fmaxf(a.y + b.y, 0.0f);
            float h2 = fmaxf(a.z + b.z, 0.0f);
            float h3 = fmaxf(a.w + b.w, 0.0f);
            __half2 lo2 = __float22half2_rn(make_float2(h0, h1));
            __half2 hi2 = __float22half2_rn(make_float2(h2, h3));
            uint2 v;
            v.x = *(uint32_t*)&lo2;
            v.y = *(uint32_t*)&hi2;
            dh[kg] = v;
        }
    }
    __syncthreads();

    // ---- MMA mainloop: warp tile 32M x 64N ----
    const int mw  = w & 1;                 // 2 M-groups of 32 rows
    const int nwp = w >> 1;                // 4 N-groups of 64 channels
    const int m0  = mw * 32;
    const int n0  = nwp * 64;

    const uint32_t sA32 = smem_u32(sA), sB32 = smem_u32(sB);

    // A: two m16k16 tiles per warp
    const uint32_t aoff = ((uint32_t)(m0 + (lane & 15)) * PADK +
                           ((lane >> 4) & 1) * 8) * 2;
    // B x4: 2 n-tiles per load
    const uint32_t boff = ((uint32_t)(n0 + ((lane >> 4) & 1) * 8 + (lane & 7)) * PADK +
                           ((lane >> 3) & 1) * 8) * 2;

    float d[2][8][4];
    #pragma unroll
    for (int mt = 0; mt < 2; mt++)
        #pragma unroll
        for (int nt = 0; nt < 8; nt++)
            { d[mt][nt][0]=0.f; d[mt][nt][1]=0.f; d[mt][nt][2]=0.f; d[mt][nt][3]=0.f; }

    #pragma unroll
    for (int k16 = 0; k16 < 8; k16++) {
        const uint32_t kb = k16 * 32;      // 16 fp16 = 32 bytes
        uint32_t a[2][4];
        #pragma unroll
        for (int mt = 0; mt < 2; mt++) {
            asm volatile(
                "ldmatrix.sync.aligned.m8n8.x4.shared.b16 {%0,%1,%2,%3}, [%4];"
                : "=r"(a[mt][0]), "=r"(a[mt][1]), "=r"(a[mt][2]), "=r"(a[mt][3])
                : "r"(sA32 + aoff + (uint32_t)mt * (16 * PADK * 2) + kb));
        }
        uint32_t b[16];
        #pragma unroll
        for (int ntp = 0; ntp < 4; ntp++) {
            asm volatile(
                "ldmatrix.sync.aligned.m8n8.x4.shared.b16 {%0,%1,%2,%3}, [%4];"
                : "=r"(b[ntp*4]), "=r"(b[ntp*4+1]), "=r"(b[ntp*4+2]), "=r"(b[ntp*4+3])
                : "r"(sB32 + boff + (uint32_t)ntp * (16 * PADK * 2) + kb));
        }
        #pragma unroll
        for (int mt = 0; mt < 2; mt++) {
            #pragma unroll
            for (int nt = 0; nt < 8; nt++) {
                const int bi = (nt >> 1) * 4 + (nt & 1) * 2;
                asm volatile(
                    "mma.sync.aligned.m16n8k16.row.col.f32.f16.f16.f32 "
                    "{%0,%1,%2,%3}, {%4,%5,%6,%7}, {%8,%9}, {%0,%1,%2,%3};"
                    : "+f"(d[mt][nt][0]), "+f"(d[mt][nt][1]),
                      "+f"(d[mt][nt][2]), "+f"(d[mt][nt][3])
                    : "r"(a[mt][0]), "r"(a[mt][1]), "r"(a[mt][2]), "r"(a[mt][3]),
                      "r"(b[bi]), "r"(b[bi+1]));
            }
        }
    }

    // ---- epilogue: max over 8 edge rows (lane bits [4:2]), write points ----
    #pragma unroll
    for (int mt = 0; mt < 2; mt++) {
        #pragma unroll
        for (int nt = 0; nt < 8; nt++) {
            float v0 = d[mt][nt][0], v1 = d[mt][nt][1];
            float v2 = d[mt][nt][2], v3 = d[mt][nt][3];
            #pragma unroll
            for (int off = 4; off <= 16; off <<= 1) {
                v0 = fmaxf(v0, __shfl_xor_sync(0xFFFFFFFFu, v0, off));
                v1 = fmaxf(v1, __shfl_xor_sync(0xFFFFFFFFu, v1, off));
                v2 = fmaxf(v2, __shfl_xor_sync(0xFFFFFFFFu, v2, off));
                v3 = fmaxf(v3, __shfl_xor_sync(0xFFFFFFFFu, v3, off));
            }
            if (lane < 4) {
                const int c = n0 + nt * 8 + lane * 2;
                const float2 bb = *(const float2*)(b4 + c);
                const int pbase = p0 + mw * 4 + mt * 2;
                float2 o0; o0.x = v0 + bb.x; o0.y = v1 + bb.y;
                float2 o1; o1.x = v2 + bb.x; o1.y = v3 + bb.y;
                *(float2*)(out + (size_t)(pbase    ) * 256 + c) = o0;
                *(float2*)(out + (size_t)(pbase + 1) * 256 + c) = o1;
            }
        }
    }
}

// ---------------- launch -----------------------------------------------------
extern "C" void kernel_launch(void* const* d_in, const int* in_sizes, int n_in,
                              void* d_out, int out_size) {
    const float* pts = (const float*)d_in[0];
    const float* W1  = (const float*)d_in[1];
    const float* b1  = (const float*)d_in[2];
    const float* W2  = (const float*)d_in[3];
    const float* b2  = (const float*)d_in[4];
    const float* W3  = (const float*)d_in[5];
    const float* b3  = (const float*)d_in[6];
    const float* W4  = (const float*)d_in[7];
    const float* b4  = (const float*)d_in[8];
    float* out = (float*)d_out;

    cudaFuncSetAttribute(conv2m_kernel,
                         cudaFuncAttributeMaxDynamicSharedMemorySize, CONV2_SMEM);

    knn_kernel  <<<NPTS/8, 256>>>(pts);
    conv1_kernel<<<NPTS/16, 512>>>(pts, W1, b1, W2, b2);
    pre2_kernel <<<NPTS/16, 256>>>(W3, b3, W4);
    conv2m_kernel<<<NPTS/8, 256, CONV2_SMEM>>>(b4, out);
}

// round 10
// speedup vs baseline: 2.1208x; 1.1902x over previous
#include <cuda_runtime.h>
#include <cuda_fp16.h>
#include <cstdint>

#define NPTS 8192
#define KNN  8

// ---------------- scratch (device globals: no allocations allowed) ----------
__device__ int   g_knn[NPTS * KNN];
__device__ unsigned short g_x1h[NPTS * 128];  // edgeconv1 output fp16 [i][k]
__device__ float g_A  [NPTS * 128];           // x1 @ (W3a - W3b) + b3
__device__ float g_B  [NPTS * 128];           // x1 @ W3b
__device__ unsigned short g_w2h[128 * 64];    // W2^T fp16 [c][u]
__device__ unsigned short g_w3h[256 * 128];   // [Wd^T ; Wb^T] fp16 [n][k]
__device__ unsigned short g_w4h[256 * 128];   // W4^T fp16 [c][k]

// ---------------- helpers ----------------------------------------------------
__device__ __forceinline__ uint32_t smem_u32(const void* p) {
    uint32_t a;
    asm("{ .reg .u64 t; cvta.to.shared.u64 t, %1; cvt.u32.u64 %0, t; }"
        : "=r"(a) : "l"(p));
    return a;
}

// ---------------- Kernel 1: KNN + weight fp16 conversion prologue -----------
__global__ __launch_bounds__(256) void knn_kernel(
    const float* __restrict__ pts,
    const float* __restrict__ W2, const float* __restrict__ W3,
    const float* __restrict__ W4)
{
    // weight conversion prologue (blocks 0..319, no syncs inside)
    {
        const int b = blockIdx.x, t = threadIdx.x;
        if (b < 64) {
            if (t < 128) {
                g_w2h[t*64 + b] = __half_as_ushort(__float2half_rn(W2[b*128 + t]));
            }
        } else if (b < 192) {
            if (t < 128) {
                int k = b - 64;
                float wa = W3[k*128 + t];
                float wb = W3[(k+128)*128 + t];
                g_w3h[t*128 + k]        = __half_as_ushort(__float2half_rn(wa - wb));
                g_w3h[(128+t)*128 + k]  = __half_as_ushort(__float2half_rn(wb));
            }
        } else if (b < 320) {
            int k = b - 192;
            g_w4h[t*128 + k] = __half_as_ushort(__float2half_rn(W4[k*256 + t]));
        }
    }

    const int TS = 2048;
    __shared__ float4 sp[TS];
    const int lane = threadIdx.x & 31;
    const int warp = threadIdx.x >> 5;
    const int qi = blockIdx.x * 8 + warp;

    const float qx = pts[qi*3+0], qy = pts[qi*3+1], qz = pts[qi*3+2];
    const float ax = -2.0f*qx, ay = -2.0f*qy, az = -2.0f*qz;

    const float INF = 3.4028235e38f;
    float    ld[8]; unsigned int li[8];
    #pragma unroll
    for (int q = 0; q < 8; q++) { ld[q] = INF; li[q] = 0xFFFFFFFFu; }

    for (int base = 0; base < NPTS; base += TS) {
        __syncthreads();
        for (int t = threadIdx.x; t < TS; t += 256) {
            float x = pts[(base+t)*3+0];
            float y = pts[(base+t)*3+1];
            float z = pts[(base+t)*3+2];
            sp[t] = make_float4(x, y, z, x*x + y*y + z*z);
        }
        __syncthreads();

        for (int jb = 0; jb < TS; jb += 256) {
            float dd[8];
            #pragma unroll
            for (int q = 0; q < 8; q++) {
                float4 p = sp[jb + q*32 + lane];
                dd[q] = fmaf(ax, p.x, fmaf(ay, p.y, fmaf(az, p.z, p.w)));
            }
            float m01 = fminf(dd[0], dd[1]), m23 = fminf(dd[2], dd[3]);
            float m45 = fminf(dd[4], dd[5]), m67 = fminf(dd[6], dd[7]);
            float mn = fminf(fminf(m01, m23), fminf(m45, m67));
            if (mn < ld[7]) {
                #pragma unroll
                for (int q = 0; q < 8; q++) {
                    float x = dd[q];
                    if (x < ld[7]) {
                        unsigned int ix = (unsigned int)(base + jb + q*32 + lane);
                        ld[7] = x; li[7] = ix;
                        #pragma unroll
                        for (int s = 6; s >= 0; s--) {
                            bool sw = ld[s+1] < ld[s];
                            float  td = sw ? ld[s] : ld[s+1];
                            unsigned int ti = sw ? li[s] : li[s+1];
                            ld[s]   = sw ? ld[s+1] : ld[s];
                            li[s]   = sw ? li[s+1] : li[s];
                            ld[s+1] = td; li[s+1] = ti;
                        }
                    }
                }
            }
        }
    }

    unsigned long long k[8];
    #pragma unroll
    for (int q = 0; q < 8; q++) {
        unsigned int ob = __float_as_uint(ld[q]);
        ob ^= ((unsigned int)((int)ob >> 31)) | 0x80000000u;
        k[q] = ((unsigned long long)ob << 32) | li[q];
    }
    #pragma unroll
    for (int r = 0; r < KNN; r++) {
        unsigned long long m = k[0];
        #pragma unroll
        for (int off = 16; off; off >>= 1) {
            unsigned long long o = __shfl_xor_sync(0xFFFFFFFFu, m, off);
            if (o < m) m = o;
        }
        if (k[0] == m) {
            #pragma unroll
            for (int s = 0; s < 7; s++) k[s] = k[s+1];
            k[7] = 0xFFFFFFFFFFFFFFFFULL;
        }
        if (lane == 0) g_knn[qi*KNN + r] = (int)(m & 0xFFFFFFFFu);
    }
}

// ---------------- Kernel 2: EdgeConv1, layer2 on tensor cores ---------------
// Per CTA: 16 points -> M=128 edge rows, N=128 (h1), K=64 (h0). fp16 mma.
#define PADK2 72
__global__ __launch_bounds__(256) void conv1_kernel(
    const float* __restrict__ pts,
    const float* __restrict__ W1, const float* __restrict__ b1,
    const float* __restrict__ b2)
{
    __shared__ float  se[16][8][6];
    __shared__ __half sE[128 * PADK2];   // A: [r=p*8+e][u]
    __shared__ __half sW[128 * PADK2];   // B: [n=c][k=u]
    const int t    = threadIdx.x;
    const int lane = t & 31;
    const int w    = t >> 5;
    const int p0   = blockIdx.x * 16;

    // stage W2^T fp16 (8192 halves = 1024 uint4)
    {
        #pragma unroll
        for (int g = 0; g < 4; g++) {
            int idx = t + g*256;           // uint4 index
            int row = idx >> 3, part = idx & 7;
            uint4 v = *((const uint4*)(g_w2h + row*64) + part);
            *((uint4*)(sW + row*PADK2) + part) = v;
        }
    }
    // edge features
    if (t < 128) {
        int p = t >> 3, e = t & 7;
        int i = p0 + p;
        int j = g_knn[i*KNN + e];
        float xi0 = pts[i*3+0], xi1 = pts[i*3+1], xi2 = pts[i*3+2];
        float xj0 = pts[j*3+0], xj1 = pts[j*3+1], xj2 = pts[j*3+2];
        se[p][e][0] = xi0; se[p][e][1] = xi1; se[p][e][2] = xi2;
        se[p][e][3] = xj0 - xi0; se[p][e][4] = xj1 - xi1; se[p][e][5] = xj2 - xi2;
    }
    __syncthreads();

    // layer 1 scalar -> sE fp16
    #pragma unroll
    for (int r = 0; r < 32; r++) {
        int id = t + r*256;                // 0..8191
        int e = id & 7, p = (id >> 3) & 15, u = id >> 7;
        float acc = b1[u];
        #pragma unroll
        for (int f = 0; f < 6; f++) acc += se[p][e][f] * W1[f*64 + u];
        sE[(p*8 + e) * PADK2 + u] = __float2half_rn(fmaxf(acc, 0.0f));
    }
    __syncthreads();

    // mma: 8 warps = 2(M) x 4(N); warp tile 64M x 32N; K=64 (4 k16 steps)
    const int mw = w & 1, nw = w >> 1;
    const int m0 = mw * 64;
    const int n0 = nw * 32;

    const uint32_t sE32 = smem_u32(sE), sW32 = smem_u32(sW);
    const uint32_t aoff = ((uint32_t)(m0 + (lane & 15)) * PADK2 +
                           ((lane >> 4) & 1) * 8) * 2;
    const uint32_t boff = ((uint32_t)(n0 + ((lane >> 4) & 1) * 8 + (lane & 7)) * PADK2 +
                           ((lane >> 3) & 1) * 8) * 2;

    float d[4][4][4];
    #pragma unroll
    for (int mt = 0; mt < 4; mt++)
        #pragma unroll
        for (int nt = 0; nt < 4; nt++)
            { d[mt][nt][0]=0.f; d[mt][nt][1]=0.f; d[mt][nt][2]=0.f; d[mt][nt][3]=0.f; }

    #pragma unroll
    for (int k16 = 0; k16 < 4; k16++) {
        const uint32_t kb = k16 * 32;      // 16 halves = 32 bytes
        uint32_t a[4][4];
        #pragma unroll
        for (int mt = 0; mt < 4; mt++) {
            asm volatile(
                "ldmatrix.sync.aligned.m8n8.x4.shared.b16 {%0,%1,%2,%3}, [%4];"
                : "=r"(a[mt][0]), "=r"(a[mt][1]), "=r"(a[mt][2]), "=r"(a[mt][3])
                : "r"(sE32 + aoff + (uint32_t)mt * (16 * PADK2 * 2) + kb));
        }
        uint32_t b[8];
        #pragma unroll
        for (int ntp = 0; ntp < 2; ntp++) {
            asm volatile(
                "ldmatrix.sync.aligned.m8n8.x4.shared.b16 {%0,%1,%2,%3}, [%4];"
                : "=r"(b[ntp*4]), "=r"(b[ntp*4+1]), "=r"(b[ntp*4+2]), "=r"(b[ntp*4+3])
                : "r"(sW32 + boff + (uint32_t)ntp * (16 * PADK2 * 2) + kb));
        }
        #pragma unroll
        for (int mt = 0; mt < 4; mt++) {
            #pragma unroll
            for (int nt = 0; nt < 4; nt++) {
                const int bi = (nt >> 1) * 4 + (nt & 1) * 2;
                asm volatile(
                    "mma.sync.aligned.m16n8k16.row.col.f32.f16.f16.f32 "
                    "{%0,%1,%2,%3}, {%4,%5,%6,%7}, {%8,%9}, {%0,%1,%2,%3};"
                    : "+f"(d[mt][nt][0]), "+f"(d[mt][nt][1]),
                      "+f"(d[mt][nt][2]), "+f"(d[mt][nt][3])
                    : "r"(a[mt][0]), "r"(a[mt][1]), "r"(a[mt][2]), "r"(a[mt][3]),
                      "r"(b[bi]), "r"(b[bi+1]));
            }
        }
    }

    // epilogue: max over 8 edge rows (lane bits [4:2]); relu; fp16 store
    #pragma unroll
    for (int mt = 0; mt < 4; mt++) {
        #pragma unroll
        for (int nt = 0; nt < 4; nt++) {
            float v0 = d[mt][nt][0], v1 = d[mt][nt][1];
            float v2 = d[mt][nt][2], v3 = d[mt][nt][3];
            #pragma unroll
            for (int off = 4; off <= 16; off <<= 1) {
                v0 = fmaxf(v0, __shfl_xor_sync(0xFFFFFFFFu, v0, off));
                v1 = fmaxf(v1, __shfl_xor_sync(0xFFFFFFFFu, v1, off));
                v2 = fmaxf(v2, __shfl_xor_sync(0xFFFFFFFFu, v2, off));
                v3 = fmaxf(v3, __shfl_xor_sync(0xFFFFFFFFu, v3, off));
            }
            if (lane < 4) {
                const int c = n0 + nt * 8 + lane * 2;
                const float2 bb = *(const float2*)(b2 + c);
                const int pA = p0 + mw * 8 + mt * 2;
                __half2 hA = __floats2half2_rn(fmaxf(v0 + bb.x, 0.0f),
                                               fmaxf(v1 + bb.y, 0.0f));
                __half2 hB = __floats2half2_rn(fmaxf(v2 + bb.x, 0.0f),
                                               fmaxf(v3 + bb.y, 0.0f));
                *(uint32_t*)(g_x1h + (size_t)(pA    ) * 128 + c) = *(uint32_t*)&hA;
                *(uint32_t*)(g_x1h + (size_t)(pA + 1) * 128 + c) = *(uint32_t*)&hB;
            }
        }
    }
}

// ---------------- Kernel 3: pre2 as fp16 GEMM -------------------------------
// Per CTA: M=64 x1 rows, N=256 ([Wd;Wb]), K=128. Writes g_A (+b3) / g_B fp32.
#define PADK 136
#define P_A_ELEMS (64  * PADK)
#define P_B_ELEMS (256 * PADK)
#define PRE2_SMEM ((P_A_ELEMS + P_B_ELEMS) * 2)

__global__ __launch_bounds__(256, 2) void pre2t_kernel(const float* __restrict__ b3)
{
    extern __shared__ __align__(16) char smem[];
    __half* sA = (__half*)smem;
    __half* sB = sA + P_A_ELEMS;

    const int t    = threadIdx.x;
    const int lane = t & 31;
    const int w    = t >> 5;
    const int i0   = blockIdx.x * 64;

    // stage A: x1 fp16 rows (64 x 128 halves = 1024 uint4)
    {
        const int r = t >> 2, q = t & 3;
        #pragma unroll
        for (int g = 0; g < 4; g++) {
            uint4 v = *((const uint4*)(g_x1h + (size_t)(i0 + r) * 128) + q*4 + g);
            *((uint4*)(sA + r * PADK) + q*4 + g) = v;
        }
    }
    // stage B: g_w3h [256][128]
    {
        const uint4* s4 = (const uint4*)(g_w3h + (size_t)t * 128);
        uint4* d4 = (uint4*)(sB + t * PADK);
        #pragma unroll
        for (int kg = 0; kg < 16; kg++) d4[kg] = s4[kg];
    }
    __syncthreads();

    const int mw  = w & 1;
    const int nwp = w >> 1;
    const int m0  = mw * 32;
    const int n0  = nwp * 64;

    const uint32_t sA32 = smem_u32(sA), sB32 = smem_u32(sB);
    const uint32_t aoff = ((uint32_t)(m0 + (lane & 15)) * PADK +
                           ((lane >> 4) & 1) * 8) * 2;
    const uint32_t boff = ((uint32_t)(n0 + ((lane >> 4) & 1) * 8 + (lane & 7)) * PADK +
                           ((lane >> 3) & 1) * 8) * 2;

    float d[2][8][4];
    #pragma unroll
    for (int mt = 0; mt < 2; mt++)
        #pragma unroll
        for (int nt = 0; nt < 8; nt++)
            { d[mt][nt][0]=0.f; d[mt][nt][1]=0.f; d[mt][nt][2]=0.f; d[mt][nt][3]=0.f; }

    #pragma unroll
    for (int k16 = 0; k16 < 8; k16++) {
        const uint32_t kb = k16 * 32;
        uint32_t a[2][4];
        #pragma unroll
        for (int mt = 0; mt < 2; mt++) {
            asm volatile(
                "ldmatrix.sync.aligned.m8n8.x4.shared.b16 {%0,%1,%2,%3}, [%4];"
                : "=r"(a[mt][0]), "=r"(a[mt][1]), "=r"(a[mt][2]), "=r"(a[mt][3])
                : "r"(sA32 + aoff + (uint32_t)mt * (16 * PADK * 2) + kb));
        }
        uint32_t b[16];
        #pragma unroll
        for (int ntp = 0; ntp < 4; ntp++) {
            asm volatile(
                "ldmatrix.sync.aligned.m8n8.x4.shared.b16 {%0,%1,%2,%3}, [%4];"
                : "=r"(b[ntp*4]), "=r"(b[ntp*4+1]), "=r"(b[ntp*4+2]), "=r"(b[ntp*4+3])
                : "r"(sB32 + boff + (uint32_t)ntp * (16 * PADK * 2) + kb));
        }
        #pragma unroll
        for (int mt = 0; mt < 2; mt++) {
            #pragma unroll
            for (int nt = 0; nt < 8; nt++) {
                const int bi = (nt >> 1) * 4 + (nt & 1) * 2;
                asm volatile(
                    "mma.sync.aligned.m16n8k16.row.col.f32.f16.f16.f32 "
                    "{%0,%1,%2,%3}, {%4,%5,%6,%7}, {%8,%9}, {%0,%1,%2,%3};"
                    : "+f"(d[mt][nt][0]), "+f"(d[mt][nt][1]),
                      "+f"(d[mt][nt][2]), "+f"(d[mt][nt][3])
                    : "r"(a[mt][0]), "r"(a[mt][1]), "r"(a[mt][2]), "r"(a[mt][3]),
                      "r"(b[bi]), "r"(b[bi+1]));
            }
        }
    }

    // epilogue: direct stores (no reduction)
    #pragma unroll
    for (int mt = 0; mt < 2; mt++) {
        const int r0 = m0 + mt*16 + (lane >> 2);
        const int iA = i0 + r0, iB = i0 + r0 + 8;
        #pragma unroll
        for (int nt = 0; nt < 8; nt++) {
            const int c = n0 + nt * 8 + (lane & 3) * 2;
            if (c < 128) {
                const float2 bb = *(const float2*)(b3 + c);
                float2 o0; o0.x = d[mt][nt][0] + bb.x; o0.y = d[mt][nt][1] + bb.y;
                float2 o1; o1.x = d[mt][nt][2] + bb.x; o1.y = d[mt][nt][3] + bb.y;
                *(float2*)(g_A + (size_t)iA * 128 + c) = o0;
                *(float2*)(g_A + (size_t)iB * 128 + c) = o1;
            } else {
                float2 o0; o0.x = d[mt][nt][0]; o0.y = d[mt][nt][1];
                float2 o1; o1.x = d[mt][nt][2]; o1.y = d[mt][nt][3];
                *(float2*)(g_B + (size_t)iA * 128 + (c - 128)) = o0;
                *(float2*)(g_B + (size_t)iB * 128 + (c - 128)) = o1;
            }
        }
    }
}

// ---------------- Kernel 4: EdgeConv2 via mma.sync fp16 (unchanged) ---------
#define A_ELEMS (64  * PADK)
#define B_ELEMS (256 * PADK)
#define CONV2_SMEM ((A_ELEMS + B_ELEMS) * 2)

__global__ __launch_bounds__(256, 2) void conv2m_kernel(
    const float* __restrict__ b4, float* __restrict__ out)
{
    extern __shared__ __align__(16) char smem[];
    __half* sA = (__half*)smem;
    __half* sB = sA + A_ELEMS;

    const int t    = threadIdx.x;
    const int lane = t & 31;
    const int w    = t >> 5;
    const int p0   = blockIdx.x * 8;

    {
        const uint4* s4 = (const uint4*)(g_w4h + (size_t)t * 128);
        uint4* d4 = (uint4*)(sB + t * PADK);
        #pragma unroll
        for (int kg = 0; kg < 16; kg++) d4[kg] = s4[kg];
    }
    {
        const int r = t >> 2, q = t & 3;
        const int i = p0 + (r >> 3);
        const int j = g_knn[i * KNN + (r & 7)];
        const float4* pa = (const float4*)(g_A + (size_t)i * 128 + q * 32);
        const float4* pb = (const float4*)(g_B + (size_t)j * 128 + q * 32);
        uint2* dh = (uint2*)(sA + r * PADK + q * 32);
        #pragma unroll
        for (int kg = 0; kg < 8; kg++) {
            float4 a = pa[kg];
            float4 b = pb[kg];
            float h0 = fmaxf(a.x + b.x, 0.0f);
            float h1 = fmaxf(a.y + b.y, 0.0f);
            float h2 = fmaxf(a.z + b.z, 0.0f);
            float h3 = fmaxf(a.w + b.w, 0.0f);
            __half2 lo2 = __float22half2_rn(make_float2(h0, h1));
            __half2 hi2 = __float22half2_rn(make_float2(h2, h3));
            uint2 v;
            v.x = *(uint32_t*)&lo2;
            v.y = *(uint32_t*)&hi2;
            dh[kg] = v;
        }
    }
    __syncthreads();

    const int mw  = w & 1;
    const int nwp = w >> 1;
    const int m0  = mw * 32;
    const int n0  = nwp * 64;

    const uint32_t sA32 = smem_u32(sA), sB32 = smem_u32(sB);
    const uint32_t aoff = ((uint32_t)(m0 + (lane & 15)) * PADK +
                           ((lane >> 4) & 1) * 8) * 2;
    const uint32_t boff = ((uint32_t)(n0 + ((lane >> 4) & 1) * 8 + (lane & 7)) * PADK +
                           ((lane >> 3) & 1) * 8) * 2;

    float d[2][8][4];
    #pragma unroll
    for (int mt = 0; mt < 2; mt++)
        #pragma unroll
        for (int nt = 0; nt < 8; nt++)
            { d[mt][nt][0]=0.f; d[mt][nt][1]=0.f; d[mt][nt][2]=0.f; d[mt][nt][3]=0.f; }

    #pragma unroll
    for (int k16 = 0; k16 < 8; k16++) {
        const uint32_t kb = k16 * 32;
        uint32_t a[2][4];
        #pragma unroll
        for (int mt = 0; mt < 2; mt++) {
            asm volatile(
                "ldmatrix.sync.aligned.m8n8.x4.shared.b16 {%0,%1,%2,%3}, [%4];"
                : "=r"(a[mt][0]), "=r"(a[mt][1]), "=r"(a[mt][2]), "=r"(a[mt][3])
                : "r"(sA32 + aoff + (uint32_t)mt * (16 * PADK * 2) + kb));
        }
        uint32_t b[16];
        #pragma unroll
        for (int ntp = 0; ntp < 4; ntp++) {
            asm volatile(
                "ldmatrix.sync.aligned.m8n8.x4.shared.b16 {%0,%1,%2,%3}, [%4];"
                : "=r"(b[ntp*4]), "=r"(b[ntp*4+1]), "=r"(b[ntp*4+2]), "=r"(b[ntp*4+3])
                : "r"(sB32 + boff + (uint32_t)ntp * (16 * PADK * 2) + kb));
        }
        #pragma unroll
        for (int mt = 0; mt < 2; mt++) {
            #pragma unroll
            for (int nt = 0; nt < 8; nt++) {
                const int bi = (nt >> 1) * 4 + (nt & 1) * 2;
                asm volatile(
                    "mma.sync.aligned.m16n8k16.row.col.f32.f16.f16.f32 "
                    "{%0,%1,%2,%3}, {%4,%5,%6,%7}, {%8,%9}, {%0,%1,%2,%3};"
                    : "+f"(d[mt][nt][0]), "+f"(d[mt][nt][1]),
                      "+f"(d[mt][nt][2]), "+f"(d[mt][nt][3])
                    : "r"(a[mt][0]), "r"(a[mt][1]), "r"(a[mt][2]), "r"(a[mt][3]),
                      "r"(b[bi]), "r"(b[bi+1]));
            }
        }
    }

    #pragma unroll
    for (int mt = 0; mt < 2; mt++) {
        #pragma unroll
        for (int nt = 0; nt < 8; nt++) {
            float v0 = d[mt][nt][0], v1 = d[mt][nt][1];
            float v2 = d[mt][nt][2], v3 = d[mt][nt][3];
            #pragma unroll
            for (int off = 4; off <= 16; off <<= 1) {
                v0 = fmaxf(v0, __shfl_xor_sync(0xFFFFFFFFu, v0, off));
                v1 = fmaxf(v1, __shfl_xor_sync(0xFFFFFFFFu, v1, off));
                v2 = fmaxf(v2, __shfl_xor_sync(0xFFFFFFFFu, v2, off));
                v3 = fmaxf(v3, __shfl_xor_sync(0xFFFFFFFFu, v3, off));
            }
            if (lane < 4) {
                const int c = n0 + nt * 8 + lane * 2;
                const float2 bb = *(const float2*)(b4 + c);
                const int pbase = p0 + mw * 4 + mt * 2;
                float2 o0; o0.x = v0 + bb.x; o0.y = v1 + bb.y;
                float2 o1; o1.x = v2 + bb.x; o1.y = v3 + bb.y;
                *(float2*)(out + (size_t)(pbase    ) * 256 + c) = o0;
                *(float2*)(out + (size_t)(pbase + 1) * 256 + c) = o1;
            }
        }
    }
}

// ---------------- launch -----------------------------------------------------
extern "C" void kernel_launch(void* const* d_in, const int* in_sizes, int n_in,
                              void* d_out, int out_size) {
    const float* pts = (const float*)d_in[0];
    const float* W1  = (const float*)d_in[1];
    const float* b1  = (const float*)d_in[2];
    const float* W2  = (const float*)d_in[3];
    const float* b2  = (const float*)d_in[4];
    const float* W3  = (const float*)d_in[5];
    const float* b3  = (const float*)d_in[6];
    const float* W4  = (const float*)d_in[7];
    const float* b4  = (const float*)d_in[8];
    float* out = (float*)d_out;

    cudaFuncSetAttribute(pre2t_kernel,
                         cudaFuncAttributeMaxDynamicSharedMemorySize, PRE2_SMEM);
    cudaFuncSetAttribute(conv2m_kernel,
                         cudaFuncAttributeMaxDynamicSharedMemorySize, CONV2_SMEM);

    knn_kernel   <<<NPTS/8, 256>>>(pts, W2, W3, W4);
    conv1_kernel <<<NPTS/16, 256>>>(pts, W1, b1, b2);
    pre2t_kernel <<<NPTS/64, 256, PRE2_SMEM>>>(b3);
    conv2m_kernel<<<NPTS/8, 256, CONV2_SMEM>>>(b4, out);
}